// round 5
// baseline (speedup 1.0000x reference)
#include <cuda_runtime.h>

// Problem constants (fixed by the dataset).
#define N_NEURONS 2000000
#define N_EDGES   16000000

// Hash table for the active set (expected <= ~100 entries).
#define HBITS 11
#define HSIZE (1 << HBITS)          // 2048 slots
#define HMASK (HSIZE - 1)
#define EMPTY_KEY 0xFFFFFFFFu

// Bloom filter: 1024 bits = 32 words = one word per smem bank (conflict-free).
#define BBITS 10
#define BMASK ((1u << BBITS) - 1u)

#define TCAP (1 << 20)              // touched-list capacity (fallback beyond)
#define ACAP (1 << 20)              // active-list capacity

// Scratch state (allocation-free __device__ globals; zero at load, and every
// launch restores the pristine state => deterministic graph replays).
__device__ float    g_x[N_NEURONS];
__device__ float    g_out[N_NEURONS];
__device__ unsigned g_act[ACAP];
__device__ unsigned g_acnt;
__device__ unsigned g_touched[TCAP];
__device__ unsigned g_tcnt[3];
__device__ unsigned g_done[4];      // last-block-done tickets, self-resetting

__device__ __forceinline__ unsigned hmix(unsigned k) { return k * 2654435761u; }

// Scatter with touched-list registration. Exactly one adder per cell observes
// old == 0.0f (atomicAdd serializes); duplicate touched entries are made
// harmless by the atomicExch in the update tail.
__device__ __forceinline__ void scatter_edge(int d, float val, int r) {
    if (val == 0.0f) return;
    float old = atomicAdd(&g_out[d], val);
    if (old == 0.0f) {
        unsigned p = atomicAdd(&g_tcnt[r], 1u);
        if (p < TCAP) g_touched[p] = (unsigned)d;
    }
}

// Last-block election. Returns true for every thread of the one block that
// arrives last. __threadfence before the ticket publishes this block's
// writes; the fence after election orders reads of other blocks' writes.
__device__ __forceinline__ bool elect_last_block(int which) {
    __shared__ unsigned s_last;
    __threadfence();
    __syncthreads();
    if (threadIdx.x == 0) {
        unsigned t = atomicAdd(&g_done[which], 1u);
        s_last = (t == gridDim.x - 1) ? 1u : 0u;
        if (s_last) g_done[which] = 0u;   // self-reset for next replay
    }
    __syncthreads();
    if (s_last) { __threadfence(); return true; }
    return false;
}

// Update tail: x += relu(out) over touched cells, out -> 0, new actives
// appended. atomicExch makes duplicate touched entries process exactly once.
__device__ void update_tail(int r, int tid, int nthr) {
    unsigned tc = g_tcnt[r];
    if (tc <= TCAP) {
        for (unsigned t = tid; t < tc; t += nthr) {
            unsigned i = g_touched[t];
            float v = atomicExch(&g_out[i], 0.0f);
            if (v > 0.0f) {
                float xo = g_x[i];
                g_x[i] = xo + v;
                if (xo == 0.0f) {
                    unsigned p = atomicAdd(&g_acnt, 1u);
                    if (p < ACAP) g_act[p] = i;
                }
            }
        }
    } else {                               // overflow fallback: full sweep
        for (unsigned i = tid; i < N_NEURONS; i += nthr) {
            float v = atomicExch(&g_out[i], 0.0f);
            if (v > 0.0f) {
                float xo = g_x[i];
                g_x[i] = xo + v;
                if (xo == 0.0f) {
                    unsigned p = atomicAdd(&g_acnt, 1u);
                    if (p < ACAP) g_act[p] = i;
                }
            }
        }
    }
}

// ---------------------------------------------------------------------------
// Start: seed x[0]=1, active={0}, counters=0 (g_x/g_out all-zero from the
// previous launch's cleanup, or from load-time zero-init).
// ---------------------------------------------------------------------------
__global__ void k_start() {
    g_x[0] = 1.0f;
    g_act[0] = 0u;
    g_acnt = 1u;
    g_tcnt[0] = 0u; g_tcnt[1] = 0u; g_tcnt[2] = 0u;
    g_out[0] = 0.0f;
}

// ---------------------------------------------------------------------------
// Layer 0: active set is exactly {0, value 1.0} -> compare only. Tail does
// the round-0 update.
// ---------------------------------------------------------------------------
__global__ void k_edge_first(const int* __restrict__ src, const int* __restrict__ dst,
                             const int* __restrict__ widx, const float* __restrict__ weights) {
    long stride = (long)gridDim.x * blockDim.x * 16;
    for (long i = ((long)blockIdx.x * blockDim.x + threadIdx.x) * 16; i < N_EDGES; i += stride) {
        int4 a0 = __ldcs(reinterpret_cast<const int4*>(src + i));
        int4 a1 = __ldcs(reinterpret_cast<const int4*>(src + i + 4));
        int4 a2 = __ldcs(reinterpret_cast<const int4*>(src + i + 8));
        int4 a3 = __ldcs(reinterpret_cast<const int4*>(src + i + 12));
        int s[16] = {a0.x,a0.y,a0.z,a0.w, a1.x,a1.y,a1.z,a1.w,
                     a2.x,a2.y,a2.z,a2.w, a3.x,a3.y,a3.z,a3.w};
        #pragma unroll
        for (int j = 0; j < 16; ++j) {
            if (s[j] == 0) {
                long e = i + j;
                scatter_edge(__ldg(dst + e), __ldg(weights + __ldg(widx + e)), 0);
            }
        }
    }
    if (elect_last_block(0)) update_tail(0, threadIdx.x, blockDim.x);
}

// ---------------------------------------------------------------------------
// Layers 1,2: Bloom pre-filter (32 smem words, bank-conflict-free broadcast)
// in front of the shared hash table. >91% of edges take the 1-LDS fast path.
// Tail does the round's update. Fallback to direct gather if set too large.
// ---------------------------------------------------------------------------
__global__ void k_edge_hash(const int* __restrict__ src, const int* __restrict__ dst,
                            const int* __restrict__ widx, const float* __restrict__ weights,
                            int layer, int round) {
    __shared__ unsigned sfilter[32];
    __shared__ unsigned sk[HSIZE];
    __shared__ float    sv[HSIZE];

    unsigned cnt = g_acnt;
    bool fallback = (cnt > (HSIZE / 2)) || (cnt > ACAP);

    if (!fallback) {
        if (threadIdx.x < 32) sfilter[threadIdx.x] = 0u;
        for (int t = threadIdx.x; t < HSIZE; t += blockDim.x) sk[t] = EMPTY_KEY;
        __syncthreads();
        for (int t = threadIdx.x; t < (int)cnt; t += blockDim.x) {
            unsigned key = g_act[t];
            float    val = g_x[key];
            unsigned m = hmix(key);
            unsigned b = (m >> 11) & BMASK;
            atomicOr(&sfilter[b >> 5], 1u << (b & 31));
            unsigned h = m >> (32 - HBITS);
            int guard = 0;
            while (atomicCAS(&sk[h], EMPTY_KEY, key) != EMPTY_KEY && sk[h] != key &&
                   ++guard < HSIZE)
                h = (h + 1) & HMASK;
            sv[h] = val;
        }
        __syncthreads();
    }

    const int* s_ptr = src + (long)layer * N_EDGES;
    long base = (long)layer * N_EDGES;
    long stride = (long)gridDim.x * blockDim.x * 16;

    for (long i = ((long)blockIdx.x * blockDim.x + threadIdx.x) * 16; i < N_EDGES; i += stride) {
        int4 a0 = __ldcs(reinterpret_cast<const int4*>(s_ptr + i));
        int4 a1 = __ldcs(reinterpret_cast<const int4*>(s_ptr + i + 4));
        int4 a2 = __ldcs(reinterpret_cast<const int4*>(s_ptr + i + 8));
        int4 a3 = __ldcs(reinterpret_cast<const int4*>(s_ptr + i + 12));
        int s[16] = {a0.x,a0.y,a0.z,a0.w, a1.x,a1.y,a1.z,a1.w,
                     a2.x,a2.y,a2.z,a2.w, a3.x,a3.y,a3.z,a3.w};
        #pragma unroll
        for (int j = 0; j < 16; ++j) {
            unsigned sj = (unsigned)s[j];
            float xv = 0.0f;
            if (fallback) {
                xv = g_x[sj];
            } else {
                unsigned m = hmix(sj);
                unsigned b = (m >> 11) & BMASK;
                if ((sfilter[b >> 5] >> (b & 31)) & 1u) {    // conflict-free LDS
                    unsigned h = m >> (32 - HBITS);
                    #pragma unroll 1
                    for (int p = 0; p < HSIZE; ++p) {
                        unsigned k = sk[h];
                        if (k == sj) { xv = sv[h]; break; }
                        if (k == EMPTY_KEY) break;
                        h = (h + 1) & HMASK;
                    }
                }
            }
            if (xv != 0.0f) {
                long e = base + i + j;
                scatter_edge(__ldg(dst + e), xv * __ldg(weights + __ldg(widx + e)), round);
            }
        }
    }
    if (elect_last_block(round)) update_tail(round, threadIdx.x, blockDim.x);
}

// ---------------------------------------------------------------------------
// Layer 3: only out[0] matters -> scan dst==0, gather x[src] on the ~8 hits.
// Tail writes the final result and restores pristine global state.
// ---------------------------------------------------------------------------
__global__ void k_edge_last(const int* __restrict__ src, const int* __restrict__ dst,
                            const int* __restrict__ widx, const float* __restrict__ weights,
                            float* __restrict__ out) {
    const long base = 3L * N_EDGES;
    const int* d_ptr = dst + base;
    long stride = (long)gridDim.x * blockDim.x * 16;
    for (long i = ((long)blockIdx.x * blockDim.x + threadIdx.x) * 16; i < N_EDGES; i += stride) {
        int4 a0 = __ldcs(reinterpret_cast<const int4*>(d_ptr + i));
        int4 a1 = __ldcs(reinterpret_cast<const int4*>(d_ptr + i + 4));
        int4 a2 = __ldcs(reinterpret_cast<const int4*>(d_ptr + i + 8));
        int4 a3 = __ldcs(reinterpret_cast<const int4*>(d_ptr + i + 12));
        int d[16] = {a0.x,a0.y,a0.z,a0.w, a1.x,a1.y,a1.z,a1.w,
                     a2.x,a2.y,a2.z,a2.w, a3.x,a3.y,a3.z,a3.w};
        #pragma unroll
        for (int j = 0; j < 16; ++j) {
            if (d[j] == 0) {
                long e = base + i + j;
                atomicAdd(&g_out[0], g_x[__ldg(src + e)] * __ldg(weights + __ldg(widx + e)));
            }
        }
    }
    if (elect_last_block(3)) {
        int tid = threadIdx.x, nthr = blockDim.x;
        if (tid == 0) out[0] = g_x[0] + fmaxf(g_out[0], 0.0f);
        // Cleanup: zero every nonzero g_x cell (active list), zero g_out[0].
        unsigned ac = g_acnt;
        if (ac <= ACAP) {
            for (unsigned t = tid; t < ac; t += nthr) g_x[g_act[t]] = 0.0f;
        } else {
            for (unsigned i = tid; i < N_NEURONS; i += nthr) g_x[i] = 0.0f;
        }
        if (tid == 0) g_out[0] = 0.0f;
    }
}

// ---------------------------------------------------------------------------
// Launch sequence (graph-capturable: kernel launches only).
// Inputs: [0]=weights f32[1024], [1]=src i32[4*16M], [2]=dst i32[4*16M],
// [3]=widx i32[4*16M]. Output: f32[1].
// ---------------------------------------------------------------------------
extern "C" void kernel_launch(void* const* d_in, const int* in_sizes, int n_in,
                              void* d_out, int out_size) {
    const float* weights = (const float*)d_in[0];
    const int*   src     = (const int*)d_in[1];
    const int*   dst     = (const int*)d_in[2];
    const int*   widx    = (const int*)d_in[3];
    float*       out     = (float*)d_out;

    const int EB = 1184, ET = 256;   // 8 CTAs/SM on 148 SMs

    k_start<<<1, 1>>>();
    k_edge_first<<<EB, ET>>>(src, dst, widx, weights);
    k_edge_hash<<<EB, ET>>>(src, dst, widx, weights, 1, 1);
    k_edge_hash<<<EB, ET>>>(src, dst, widx, weights, 2, 2);
    k_edge_last<<<EB, ET>>>(src, dst, widx, weights, out);
}

// round 6
// speedup vs baseline: 1.0717x; 1.0717x over previous
#include <cuda_runtime.h>

// Problem constants (fixed by the dataset).
#define N_NEURONS 2000000
#define N_EDGES   16000000

// Hash table for the active set (expected <= ~100 entries).
#define HBITS 11
#define HSIZE (1 << HBITS)          // 2048 slots
#define HMASK (HSIZE - 1)
#define EMPTY_KEY 0xFFFFFFFFu

// Bloom filter: 1024 bits = 32 words = one word per smem bank. Same-bank
// access implies same-word => broadcast => conflict-free by construction.
#define BBITS 10
#define BMASK ((1u << BBITS) - 1u)

#define TCAP (1 << 20)              // touched-list capacity (fallback beyond)
#define ACAP (1 << 20)              // active-list capacity

// Scratch state (allocation-free __device__ globals; zero at load, and every
// launch restores the pristine state => deterministic graph replays).
__device__ float    g_x[N_NEURONS];
__device__ float    g_out[N_NEURONS];
__device__ unsigned g_act[ACAP];
__device__ unsigned g_acnt;
__device__ unsigned g_touched[TCAP];
__device__ unsigned g_tcnt[3];
__device__ unsigned g_done[4];      // last-block-done tickets, self-resetting

__device__ __forceinline__ unsigned hmix(unsigned k) { return k * 2654435761u; }

// Scatter with touched-list registration. Exactly one adder per cell observes
// old == 0.0f (atomicAdd serializes); duplicate touched entries are made
// harmless by the atomicExch in the update tail.
__device__ __forceinline__ void scatter_edge(int d, float val, int r) {
    if (val == 0.0f) return;
    float old = atomicAdd(&g_out[d], val);
    if (old == 0.0f) {
        unsigned p = atomicAdd(&g_tcnt[r], 1u);
        if (p < TCAP) g_touched[p] = (unsigned)d;
    }
}

// Last-block election. Returns true for every thread of the one block that
// arrives last. __threadfence before the ticket publishes this block's
// writes; the fence after election orders reads of other blocks' writes.
__device__ __forceinline__ bool elect_last_block(int which) {
    __shared__ unsigned s_last;
    __threadfence();
    __syncthreads();
    if (threadIdx.x == 0) {
        unsigned t = atomicAdd(&g_done[which], 1u);
        s_last = (t == gridDim.x - 1) ? 1u : 0u;
        if (s_last) g_done[which] = 0u;   // self-reset for next replay
    }
    __syncthreads();
    if (s_last) { __threadfence(); return true; }
    return false;
}

// Update tail: x += relu(out) over touched cells, out -> 0, new actives
// appended. atomicExch makes duplicate touched entries process exactly once.
__device__ void update_tail(int r, int tid, int nthr) {
    unsigned tc = g_tcnt[r];
    if (tc <= TCAP) {
        for (unsigned t = tid; t < tc; t += nthr) {
            unsigned i = g_touched[t];
            float v = atomicExch(&g_out[i], 0.0f);
            if (v > 0.0f) {
                float xo = g_x[i];
                g_x[i] = xo + v;
                if (xo == 0.0f) {
                    unsigned p = atomicAdd(&g_acnt, 1u);
                    if (p < ACAP) g_act[p] = i;
                }
            }
        }
    } else {                               // overflow fallback: full sweep
        for (unsigned i = tid; i < N_NEURONS; i += nthr) {
            float v = atomicExch(&g_out[i], 0.0f);
            if (v > 0.0f) {
                float xo = g_x[i];
                g_x[i] = xo + v;
                if (xo == 0.0f) {
                    unsigned p = atomicAdd(&g_acnt, 1u);
                    if (p < ACAP) g_act[p] = i;
                }
            }
        }
    }
}

// ---------------------------------------------------------------------------
// Start: seed x[0]=1, active={0}, counters=0 (g_x/g_out all-zero from the
// previous launch's cleanup, or from load-time zero-init).
// ---------------------------------------------------------------------------
__global__ void k_start() {
    g_x[0] = 1.0f;
    g_act[0] = 0u;
    g_acnt = 1u;
    g_tcnt[0] = 0u; g_tcnt[1] = 0u; g_tcnt[2] = 0u;
    g_out[0] = 0.0f;
}

// ---------------------------------------------------------------------------
// Layer 0: active set is exactly {0, value 1.0} -> compare only. Tail does
// the round-0 update.
// ---------------------------------------------------------------------------
__global__ void __launch_bounds__(256, 8)
k_edge_first(const int* __restrict__ src, const int* __restrict__ dst,
             const int* __restrict__ widx, const float* __restrict__ weights) {
    long stride = (long)gridDim.x * blockDim.x * 8;
    for (long i = ((long)blockIdx.x * blockDim.x + threadIdx.x) * 8; i < N_EDGES; i += stride) {
        int4 a = __ldcs(reinterpret_cast<const int4*>(src + i));
        int4 b = __ldcs(reinterpret_cast<const int4*>(src + i + 4));
        if (a.x == 0) scatter_edge(__ldg(dst + i),     __ldg(weights + __ldg(widx + i)),     0);
        if (a.y == 0) scatter_edge(__ldg(dst + i + 1), __ldg(weights + __ldg(widx + i + 1)), 0);
        if (a.z == 0) scatter_edge(__ldg(dst + i + 2), __ldg(weights + __ldg(widx + i + 2)), 0);
        if (a.w == 0) scatter_edge(__ldg(dst + i + 3), __ldg(weights + __ldg(widx + i + 3)), 0);
        if (b.x == 0) scatter_edge(__ldg(dst + i + 4), __ldg(weights + __ldg(widx + i + 4)), 0);
        if (b.y == 0) scatter_edge(__ldg(dst + i + 5), __ldg(weights + __ldg(widx + i + 5)), 0);
        if (b.z == 0) scatter_edge(__ldg(dst + i + 6), __ldg(weights + __ldg(widx + i + 6)), 0);
        if (b.w == 0) scatter_edge(__ldg(dst + i + 7), __ldg(weights + __ldg(widx + i + 7)), 0);
    }
    if (elect_last_block(0)) update_tail(0, threadIdx.x, blockDim.x);
}

// ---------------------------------------------------------------------------
// Layers 1,2: Bloom pre-filter (conflict-free) in front of the shared hash
// table; >91% of edges resolve with one broadcast LDS + bit test. Tail does
// the round's update. Fallback to direct gather if the set is too large.
// ---------------------------------------------------------------------------
__device__ __forceinline__ float probe_one(unsigned sj, const unsigned* sfilter,
                                           const unsigned* sk, const float* sv) {
    unsigned m = hmix(sj);
    unsigned b = (m >> 11) & BMASK;
    if (!((sfilter[b >> 5] >> (b & 31)) & 1u)) return 0.0f;
    unsigned h = m >> (32 - HBITS);
    #pragma unroll 1
    for (int p = 0; p < HSIZE; ++p) {
        unsigned k = sk[h];
        if (k == sj) return sv[h];
        if (k == EMPTY_KEY) return 0.0f;
        h = (h + 1) & HMASK;
    }
    return 0.0f;
}

__global__ void __launch_bounds__(256, 8)
k_edge_hash(const int* __restrict__ src, const int* __restrict__ dst,
            const int* __restrict__ widx, const float* __restrict__ weights,
            int layer, int round) {
    __shared__ unsigned sfilter[32];
    __shared__ unsigned sk[HSIZE];
    __shared__ float    sv[HSIZE];

    unsigned cnt = g_acnt;
    bool fallback = (cnt > (HSIZE / 2)) || (cnt > ACAP);

    if (!fallback) {
        if (threadIdx.x < 32) sfilter[threadIdx.x] = 0u;
        for (int t = threadIdx.x; t < HSIZE; t += blockDim.x) sk[t] = EMPTY_KEY;
        __syncthreads();
        for (int t = threadIdx.x; t < (int)cnt; t += blockDim.x) {
            unsigned key = g_act[t];
            float    val = g_x[key];
            unsigned m = hmix(key);
            unsigned b = (m >> 11) & BMASK;
            atomicOr(&sfilter[b >> 5], 1u << (b & 31));
            unsigned h = m >> (32 - HBITS);
            int guard = 0;
            while (atomicCAS(&sk[h], EMPTY_KEY, key) != EMPTY_KEY && sk[h] != key &&
                   ++guard < HSIZE)
                h = (h + 1) & HMASK;
            sv[h] = val;
        }
        __syncthreads();
    }

    const int* s_ptr = src + (long)layer * N_EDGES;
    long base = (long)layer * N_EDGES;
    long stride = (long)gridDim.x * blockDim.x * 8;

    for (long i = ((long)blockIdx.x * blockDim.x + threadIdx.x) * 8; i < N_EDGES; i += stride) {
        int4 a = __ldcs(reinterpret_cast<const int4*>(s_ptr + i));
        int4 b = __ldcs(reinterpret_cast<const int4*>(s_ptr + i + 4));
        #pragma unroll
        for (int j = 0; j < 8; ++j) {
            int sj_i = (j == 0) ? a.x : (j == 1) ? a.y : (j == 2) ? a.z : (j == 3) ? a.w
                     : (j == 4) ? b.x : (j == 5) ? b.y : (j == 6) ? b.z : b.w;
            unsigned sj = (unsigned)sj_i;
            float xv = fallback ? g_x[sj] : probe_one(sj, sfilter, sk, sv);
            if (xv != 0.0f) {
                long e = base + i + j;
                scatter_edge(__ldg(dst + e), xv * __ldg(weights + __ldg(widx + e)), round);
            }
        }
    }
    if (elect_last_block(round)) update_tail(round, threadIdx.x, blockDim.x);
}

// ---------------------------------------------------------------------------
// Layer 3: only out[0] matters -> scan dst==0, gather x[src] on the ~8 hits.
// Tail writes the final result and restores pristine global state.
// ---------------------------------------------------------------------------
__global__ void __launch_bounds__(256, 8)
k_edge_last(const int* __restrict__ src, const int* __restrict__ dst,
            const int* __restrict__ widx, const float* __restrict__ weights,
            float* __restrict__ out) {
    const long base = 3L * N_EDGES;
    const int* d_ptr = dst + base;
    long stride = (long)gridDim.x * blockDim.x * 8;
    for (long i = ((long)blockIdx.x * blockDim.x + threadIdx.x) * 8; i < N_EDGES; i += stride) {
        int4 a = __ldcs(reinterpret_cast<const int4*>(d_ptr + i));
        int4 b = __ldcs(reinterpret_cast<const int4*>(d_ptr + i + 4));
        #pragma unroll
        for (int j = 0; j < 8; ++j) {
            int dj = (j == 0) ? a.x : (j == 1) ? a.y : (j == 2) ? a.z : (j == 3) ? a.w
                   : (j == 4) ? b.x : (j == 5) ? b.y : (j == 6) ? b.z : b.w;
            if (dj == 0) {
                long e = base + i + j;
                atomicAdd(&g_out[0], g_x[__ldg(src + e)] * __ldg(weights + __ldg(widx + e)));
            }
        }
    }
    if (elect_last_block(3)) {
        int tid = threadIdx.x, nthr = blockDim.x;
        if (tid == 0) out[0] = g_x[0] + fmaxf(g_out[0], 0.0f);
        // Cleanup: zero every nonzero g_x cell (active list), zero g_out[0].
        unsigned ac = g_acnt;
        if (ac <= ACAP) {
            for (unsigned t = tid; t < ac; t += nthr) g_x[g_act[t]] = 0.0f;
        } else {
            for (unsigned i = tid; i < N_NEURONS; i += nthr) g_x[i] = 0.0f;
        }
        if (tid == 0) g_out[0] = 0.0f;
    }
}

// ---------------------------------------------------------------------------
// Launch sequence (graph-capturable: kernel launches only).
// Inputs: [0]=weights f32[1024], [1]=src i32[4*16M], [2]=dst i32[4*16M],
// [3]=widx i32[4*16M]. Output: f32[1].
// ---------------------------------------------------------------------------
extern "C" void kernel_launch(void* const* d_in, const int* in_sizes, int n_in,
                              void* d_out, int out_size) {
    const float* weights = (const float*)d_in[0];
    const int*   src     = (const int*)d_in[1];
    const int*   dst     = (const int*)d_in[2];
    const int*   widx    = (const int*)d_in[3];
    float*       out     = (float*)d_out;

    const int EB = 1184, ET = 256;   // 8 CTAs/SM on 148 SMs

    k_start<<<1, 1>>>();
    k_edge_first<<<EB, ET>>>(src, dst, widx, weights);
    k_edge_hash<<<EB, ET>>>(src, dst, widx, weights, 1, 1);
    k_edge_hash<<<EB, ET>>>(src, dst, widx, weights, 2, 2);
    k_edge_last<<<EB, ET>>>(src, dst, widx, weights, out);
}

// round 7
// speedup vs baseline: 1.1696x; 1.0914x over previous
#include <cuda_runtime.h>

// Problem constants (fixed by the dataset).
#define N_NEURONS 2000000u
#define N_EDGES   16000000u

// Direct-mapped open-addressing table: paired (key,value) in uint2 so one
// LDS.64 serves the whole probe. Index = key & HMASK (keys are uniform).
#define HBITS 11
#define HSIZE (1 << HBITS)          // 2048 slots = 16KB
#define HMASK (HSIZE - 1)
#define EMPTY_KEY 0xFFFFFFFFu

#define TCAP (1 << 20)              // touched-list capacity (fallback beyond)
#define ACAP (1 << 20)              // active-list capacity

// Scratch state (allocation-free __device__ globals; zero at load, and every
// launch restores the pristine state => deterministic graph replays).
__device__ float    g_x[N_NEURONS];
__device__ float    g_out[N_NEURONS];
__device__ unsigned g_act[ACAP];
__device__ unsigned g_acnt;
__device__ unsigned g_touched[TCAP];
__device__ unsigned g_tcnt[3];
__device__ unsigned g_done[4];      // last-block-done tickets, self-resetting

// Scatter with touched-list registration. Exactly one adder per cell observes
// old == 0.0f (atomicAdd serializes); duplicate touched entries are made
// harmless by the atomicExch in the update tail.
__device__ __forceinline__ void scatter_edge(int d, float val, int r) {
    if (val == 0.0f) return;
    float old = atomicAdd(&g_out[d], val);
    if (old == 0.0f) {
        unsigned p = atomicAdd(&g_tcnt[r], 1u);
        if (p < TCAP) g_touched[p] = (unsigned)d;
    }
}

// Last-block election. Returns true for every thread of the one block that
// arrives last. __threadfence before the ticket publishes this block's
// writes; the fence after election orders reads of other blocks' writes.
__device__ __forceinline__ bool elect_last_block(int which) {
    __shared__ unsigned s_last;
    __threadfence();
    __syncthreads();
    if (threadIdx.x == 0) {
        unsigned t = atomicAdd(&g_done[which], 1u);
        s_last = (t == gridDim.x - 1) ? 1u : 0u;
        if (s_last) g_done[which] = 0u;   // self-reset for next replay
    }
    __syncthreads();
    if (s_last) { __threadfence(); return true; }
    return false;
}

// Update tail: x += relu(out) over touched cells, out -> 0, new actives
// appended. atomicExch makes duplicate touched entries process exactly once.
__device__ void update_tail(int r, int tid, int nthr) {
    unsigned tc = g_tcnt[r];
    if (tc <= TCAP) {
        for (unsigned t = tid; t < tc; t += nthr) {
            unsigned i = g_touched[t];
            float v = atomicExch(&g_out[i], 0.0f);
            if (v > 0.0f) {
                float xo = g_x[i];
                g_x[i] = xo + v;
                if (xo == 0.0f) {
                    unsigned p = atomicAdd(&g_acnt, 1u);
                    if (p < ACAP) g_act[p] = i;
                }
            }
        }
    } else {                               // overflow fallback: full sweep
        for (unsigned i = tid; i < N_NEURONS; i += nthr) {
            float v = atomicExch(&g_out[i], 0.0f);
            if (v > 0.0f) {
                float xo = g_x[i];
                g_x[i] = xo + v;
                if (xo == 0.0f) {
                    unsigned p = atomicAdd(&g_acnt, 1u);
                    if (p < ACAP) g_act[p] = i;
                }
            }
        }
    }
}

// ---------------------------------------------------------------------------
// Start: seed x[0]=1, active={0}, counters=0 (g_x/g_out all-zero from the
// previous launch's cleanup, or from load-time zero-init).
// ---------------------------------------------------------------------------
__global__ void k_start() {
    g_x[0] = 1.0f;
    g_act[0] = 0u;
    g_acnt = 1u;
    g_tcnt[0] = 0u; g_tcnt[1] = 0u; g_tcnt[2] = 0u;
    g_out[0] = 0.0f;
}

// ---------------------------------------------------------------------------
// Layer 0: active set is exactly {0, value 1.0} -> compare only. Pointers are
// pre-offset by the host; all indexing is 32-bit. Tail does round-0 update.
// ---------------------------------------------------------------------------
__global__ void __launch_bounds__(256, 8)
k_edge_first(const int* __restrict__ src, const int* __restrict__ dst,
             const int* __restrict__ widx, const float* __restrict__ weights) {
    unsigned stride = gridDim.x * blockDim.x * 8u;
    for (unsigned i = (blockIdx.x * blockDim.x + threadIdx.x) * 8u; i < N_EDGES; i += stride) {
        int4 a = __ldcs(reinterpret_cast<const int4*>(src + i));
        int4 b = __ldcs(reinterpret_cast<const int4*>(src + i + 4));
        int s[8] = {a.x, a.y, a.z, a.w, b.x, b.y, b.z, b.w};
        #pragma unroll
        for (int j = 0; j < 8; ++j) {
            if (s[j] == 0) {
                unsigned e = i + j;
                scatter_edge(__ldg(dst + e), __ldg(weights + __ldg(widx + e)), 0);
            }
        }
    }
    if (elect_last_block(0)) update_tail(0, threadIdx.x, blockDim.x);
}

// ---------------------------------------------------------------------------
// Layers 1,2: direct-mapped paired-table probe. Fast path per edge:
//   AND -> LDS.64 {key,val} -> compare (empty ~96% / hit / foreign ~4%).
// Linear probing only on foreign-key collision. Fallback to direct gather if
// the active set exceeds half the table.
// ---------------------------------------------------------------------------
__global__ void __launch_bounds__(256, 8)
k_edge_hash(const int* __restrict__ src, const int* __restrict__ dst,
            const int* __restrict__ widx, const float* __restrict__ weights,
            int round) {
    __shared__ uint2 stab[HSIZE];     // .x = key, .y = float bits

    unsigned cnt = g_acnt;
    bool fallback = (cnt > (HSIZE / 2)) || (cnt > ACAP);

    if (!fallback) {
        for (int t = threadIdx.x; t < HSIZE; t += blockDim.x)
            stab[t].x = EMPTY_KEY;
        __syncthreads();
        for (int t = threadIdx.x; t < (int)cnt; t += blockDim.x) {
            unsigned key = g_act[t];
            unsigned vbits = __float_as_uint(g_x[key]);
            unsigned h = key & HMASK;
            int guard = 0;
            while (atomicCAS(&stab[h].x, EMPTY_KEY, key) != EMPTY_KEY &&
                   stab[h].x != key && ++guard < HSIZE)
                h = (h + 1) & HMASK;
            stab[h].y = vbits;
        }
        __syncthreads();
    }

    unsigned stride = gridDim.x * blockDim.x * 8u;
    for (unsigned i = (blockIdx.x * blockDim.x + threadIdx.x) * 8u; i < N_EDGES; i += stride) {
        int4 a = __ldcs(reinterpret_cast<const int4*>(src + i));
        int4 b = __ldcs(reinterpret_cast<const int4*>(src + i + 4));
        int s[8] = {a.x, a.y, a.z, a.w, b.x, b.y, b.z, b.w};
        #pragma unroll
        for (int j = 0; j < 8; ++j) {
            unsigned sj = (unsigned)s[j];
            float xv;
            if (fallback) {
                xv = g_x[sj];
            } else {
                uint2 kv = stab[sj & HMASK];
                if (kv.x == sj) {
                    xv = __uint_as_float(kv.y);          // direct hit
                } else if (kv.x == EMPTY_KEY) {
                    xv = 0.0f;                           // definite miss (~96%)
                } else {
                    xv = 0.0f;                           // collision: probe chain
                    unsigned h = sj & HMASK;
                    #pragma unroll 1
                    for (int p = 0; p < HSIZE; ++p) {
                        h = (h + 1) & HMASK;
                        uint2 kv2 = stab[h];
                        if (kv2.x == sj) { xv = __uint_as_float(kv2.y); break; }
                        if (kv2.x == EMPTY_KEY) break;
                    }
                }
            }
            if (xv != 0.0f) {
                unsigned e = i + j;
                scatter_edge(__ldg(dst + e), xv * __ldg(weights + __ldg(widx + e)), round);
            }
        }
    }
    if (elect_last_block(round)) update_tail(round, threadIdx.x, blockDim.x);
}

// ---------------------------------------------------------------------------
// Layer 3: only out[0] matters -> scan dst==0, gather x[src] on the ~8 hits.
// Tail writes the final result and restores pristine global state.
// ---------------------------------------------------------------------------
__global__ void __launch_bounds__(256, 8)
k_edge_last(const int* __restrict__ src, const int* __restrict__ dst,
            const int* __restrict__ widx, const float* __restrict__ weights,
            float* __restrict__ out) {
    unsigned stride = gridDim.x * blockDim.x * 8u;
    for (unsigned i = (blockIdx.x * blockDim.x + threadIdx.x) * 8u; i < N_EDGES; i += stride) {
        int4 a = __ldcs(reinterpret_cast<const int4*>(dst + i));
        int4 b = __ldcs(reinterpret_cast<const int4*>(dst + i + 4));
        int d[8] = {a.x, a.y, a.z, a.w, b.x, b.y, b.z, b.w};
        #pragma unroll
        for (int j = 0; j < 8; ++j) {
            if (d[j] == 0) {
                unsigned e = i + j;
                atomicAdd(&g_out[0], g_x[__ldg(src + e)] * __ldg(weights + __ldg(widx + e)));
            }
        }
    }
    if (elect_last_block(3)) {
        int tid = threadIdx.x, nthr = blockDim.x;
        if (tid == 0) out[0] = g_x[0] + fmaxf(g_out[0], 0.0f);
        // Cleanup: zero every nonzero g_x cell (active list), zero g_out[0].
        unsigned ac = g_acnt;
        if (ac <= ACAP) {
            for (unsigned t = tid; t < ac; t += nthr) g_x[g_act[t]] = 0.0f;
        } else {
            for (unsigned i = tid; i < N_NEURONS; i += nthr) g_x[i] = 0.0f;
        }
        if (tid == 0) g_out[0] = 0.0f;
    }
}

// ---------------------------------------------------------------------------
// Launch sequence (graph-capturable: kernel launches only). Per-layer edge
// pointers are pre-offset here so all device indexing is 32-bit.
// Inputs: [0]=weights f32[1024], [1]=src i32[4*16M], [2]=dst i32[4*16M],
// [3]=widx i32[4*16M]. Output: f32[1].
// ---------------------------------------------------------------------------
extern "C" void kernel_launch(void* const* d_in, const int* in_sizes, int n_in,
                              void* d_out, int out_size) {
    const float* weights = (const float*)d_in[0];
    const int*   src     = (const int*)d_in[1];
    const int*   dst     = (const int*)d_in[2];
    const int*   widx    = (const int*)d_in[3];
    float*       out     = (float*)d_out;

    const int EB = 1184, ET = 256;   // 8 CTAs/SM on 148 SMs
    const size_t E = (size_t)N_EDGES;

    k_start<<<1, 1>>>();
    k_edge_first<<<EB, ET>>>(src, dst, widx, weights);
    k_edge_hash<<<EB, ET>>>(src + E,   dst + E,   widx + E,   weights, 1);
    k_edge_hash<<<EB, ET>>>(src + 2*E, dst + 2*E, widx + 2*E, weights, 2);
    k_edge_last<<<EB, ET>>>(src + 3*E, dst + 3*E, widx + 3*E, weights, out);
}

// round 10
// speedup vs baseline: 1.2220x; 1.0448x over previous
#include <cuda_runtime.h>

// Problem constants (fixed by the dataset).
#define N_NEURONS 2000000u
#define N_EDGES   16000000u

// Per-lane-column bit filter: CWORDS words per lane-column, 32 columns.
// Word index = w*32 + lane  =>  bank == lane  =>  conflict-free always.
#define CWORDS 128                        // 4096 bits per column
#define FILT_WORDS (CWORDS * 32)          // 4096 words = 16KB

#define TCAP (1 << 20)                    // touched-list capacity
#define ACAP (1 << 20)                    // active-list capacity

// Scratch state (allocation-free __device__ globals; zero at load, and every
// launch restores the pristine state => deterministic graph replays).
__device__ float    g_x[N_NEURONS];
__device__ float    g_out[N_NEURONS];
__device__ unsigned g_act[ACAP];
__device__ unsigned g_acnt;
__device__ unsigned g_touched[TCAP];
__device__ unsigned g_tcnt[3];
__device__ unsigned g_done[4];            // last-block tickets, self-resetting

// hash -> (word-in-column, 2 bit positions)
__device__ __forceinline__ unsigned hmix(unsigned k) { return k * 2654435761u; }

// Scatter with touched-list registration. Exactly one adder per cell observes
// old == 0.0f; duplicate touched entries are defused by atomicExch in the tail.
__device__ __forceinline__ void scatter_edge(int d, float val, int r) {
    if (val == 0.0f) return;
    float old = atomicAdd(&g_out[d], val);
    if (old == 0.0f) {
        unsigned p = atomicAdd(&g_tcnt[r], 1u);
        if (p < TCAP) g_touched[p] = (unsigned)d;
    }
}

// Last-block election: true for every thread of the block that arrives last.
__device__ __forceinline__ bool elect_last_block(int which) {
    __shared__ unsigned s_last;
    __threadfence();
    __syncthreads();
    if (threadIdx.x == 0) {
        unsigned t = atomicAdd(&g_done[which], 1u);
        s_last = (t == gridDim.x - 1) ? 1u : 0u;
        if (s_last) g_done[which] = 0u;   // self-reset for next replay
    }
    __syncthreads();
    if (s_last) { __threadfence(); return true; }
    return false;
}

// Update tail: x += relu(out) over touched cells, out -> 0, new actives
// appended. atomicExch makes duplicate touched entries process exactly once.
__device__ void update_tail(int r, int tid, int nthr) {
    unsigned tc = g_tcnt[r];
    if (tc <= TCAP) {
        for (unsigned t = tid; t < tc; t += nthr) {
            unsigned i = g_touched[t];
            float v = atomicExch(&g_out[i], 0.0f);
            if (v > 0.0f) {
                float xo = g_x[i];
                g_x[i] = xo + v;
                if (xo == 0.0f) {
                    unsigned p = atomicAdd(&g_acnt, 1u);
                    if (p < ACAP) g_act[p] = i;
                }
            }
        }
    } else {                               // overflow fallback: full sweep
        for (unsigned i = tid; i < N_NEURONS; i += nthr) {
            float v = atomicExch(&g_out[i], 0.0f);
            if (v > 0.0f) {
                float xo = g_x[i];
                g_x[i] = xo + v;
                if (xo == 0.0f) {
                    unsigned p = atomicAdd(&g_acnt, 1u);
                    if (p < ACAP) g_act[p] = i;
                }
            }
        }
    }
}

// ---------------------------------------------------------------------------
// Start: seed x[0]=1, active={0}, counters=0.
// ---------------------------------------------------------------------------
__global__ void k_start() {
    g_x[0] = 1.0f;
    g_act[0] = 0u;
    g_acnt = 1u;
    g_tcnt[0] = 0u; g_tcnt[1] = 0u; g_tcnt[2] = 0u;
    g_out[0] = 0.0f;
}

// ---------------------------------------------------------------------------
// Layer 0: active set is exactly {0, value 1.0} -> compare only.
// ---------------------------------------------------------------------------
__global__ void __launch_bounds__(256, 8)
k_edge_first(const int* __restrict__ src, const int* __restrict__ dst,
             const int* __restrict__ widx, const float* __restrict__ weights) {
    unsigned stride = gridDim.x * blockDim.x * 8u;
    for (unsigned i = (blockIdx.x * blockDim.x + threadIdx.x) * 8u; i < N_EDGES; i += stride) {
        int4 a = __ldcs(reinterpret_cast<const int4*>(src + i));
        int4 b = __ldcs(reinterpret_cast<const int4*>(src + i + 4));
        int s[8] = {a.x, a.y, a.z, a.w, b.x, b.y, b.z, b.w};
        #pragma unroll
        for (int j = 0; j < 8; ++j) {
            if (s[j] == 0) {
                unsigned e = i + j;
                scatter_edge(__ldg(dst + e), __ldg(weights + __ldg(widx + e)), 0);
            }
        }
    }
    if (elect_last_block(0)) update_tail(0, threadIdx.x, blockDim.x);
}

// ---------------------------------------------------------------------------
// Layers 1,2: per-lane-column bit filter. Per edge: hash -> conflict-free
// LDS.32 in this lane's column -> 2-bit mask test. On pass (true hit or ~0.2%
// false positive) gather g_x[sj] from global — correct either way, since
// g_x of inactive neurons is 0. No table, no probe loop, no fallback needed.
// ---------------------------------------------------------------------------
__global__ void __launch_bounds__(256, 8)
k_edge_filter(const int* __restrict__ src, const int* __restrict__ dst,
              const int* __restrict__ widx, const float* __restrict__ weights,
              int round) {
    __shared__ unsigned sfilt[FILT_WORDS];

    // Zero the filter.
    for (int t = threadIdx.x; t < FILT_WORDS; t += blockDim.x) sfilt[t] = 0u;
    __syncthreads();

    // Build: every (key, column) pair sets 2 hash bits in that column's word.
    // Consecutive threads share a key (broadcast load) and hit consecutive
    // lanes (coalesced, conflict-free smem atomics). cnt*32 items, cnt tiny.
    unsigned cnt = g_acnt;
    if (cnt > ACAP) cnt = ACAP;
    for (unsigned t = threadIdx.x; t < cnt * 32u; t += blockDim.x) {
        unsigned key = g_act[t >> 5];
        unsigned col = t & 31u;
        unsigned m = hmix(key);
        unsigned w = (m >> 25) & (CWORDS - 1);
        unsigned mask = (1u << ((m >> 20) & 31u)) | (1u << ((m >> 15) & 31u));
        atomicOr(&sfilt[(w << 5) + col], mask);
    }
    __syncthreads();

    const unsigned lane = threadIdx.x & 31u;
    unsigned stride = gridDim.x * blockDim.x * 8u;

    for (unsigned i = (blockIdx.x * blockDim.x + threadIdx.x) * 8u; i < N_EDGES; i += stride) {
        int4 a = __ldcs(reinterpret_cast<const int4*>(src + i));
        int4 b = __ldcs(reinterpret_cast<const int4*>(src + i + 4));
        int s[8] = {a.x, a.y, a.z, a.w, b.x, b.y, b.z, b.w};
        #pragma unroll
        for (int j = 0; j < 8; ++j) {
            unsigned sj = (unsigned)s[j];
            unsigned m = hmix(sj);
            unsigned w = (m >> 25) & (CWORDS - 1);
            unsigned mask = (1u << ((m >> 20) & 31u)) | (1u << ((m >> 15) & 31u));
            unsigned word = sfilt[(w << 5) + lane];      // bank == lane: conflict-free
            if ((word & mask) == mask) {
                float xv = g_x[sj];                      // 0.0 if false positive
                if (xv != 0.0f) {
                    unsigned e = i + j;
                    scatter_edge(__ldg(dst + e), xv * __ldg(weights + __ldg(widx + e)), round);
                }
            }
        }
    }
    if (elect_last_block(round)) update_tail(round, threadIdx.x, blockDim.x);
}

// ---------------------------------------------------------------------------
// Layer 3: only out[0] matters -> scan dst==0, gather x[src] on the ~8 hits.
// Tail writes the final result and restores pristine global state.
// ---------------------------------------------------------------------------
__global__ void __launch_bounds__(256, 8)
k_edge_last(const int* __restrict__ src, const int* __restrict__ dst,
            const int* __restrict__ widx, const float* __restrict__ weights,
            float* __restrict__ out) {
    unsigned stride = gridDim.x * blockDim.x * 8u;
    for (unsigned i = (blockIdx.x * blockDim.x + threadIdx.x) * 8u; i < N_EDGES; i += stride) {
        int4 a = __ldcs(reinterpret_cast<const int4*>(dst + i));
        int4 b = __ldcs(reinterpret_cast<const int4*>(dst + i + 4));
        int d[8] = {a.x, a.y, a.z, a.w, b.x, b.y, b.z, b.w};
        #pragma unroll
        for (int j = 0; j < 8; ++j) {
            if (d[j] == 0) {
                unsigned e = i + j;
                atomicAdd(&g_out[0], g_x[__ldg(src + e)] * __ldg(weights + __ldg(widx + e)));
            }
        }
    }
    if (elect_last_block(3)) {
        int tid = threadIdx.x, nthr = blockDim.x;
        if (tid == 0) out[0] = g_x[0] + fmaxf(g_out[0], 0.0f);
        // Cleanup: zero every nonzero g_x cell (active list), zero g_out[0].
        unsigned ac = g_acnt;
        if (ac <= ACAP) {
            for (unsigned t = tid; t < ac; t += nthr) g_x[g_act[t]] = 0.0f;
        } else {
            for (unsigned i = tid; i < N_NEURONS; i += nthr) g_x[i] = 0.0f;
        }
        if (tid == 0) g_out[0] = 0.0f;
    }
}

// ---------------------------------------------------------------------------
// Launch sequence (graph-capturable: kernel launches only). Per-layer edge
// pointers pre-offset on the host so device indexing stays 32-bit.
// Inputs: [0]=weights f32[1024], [1]=src i32[4*16M], [2]=dst i32[4*16M],
// [3]=widx i32[4*16M]. Output: f32[1].
// ---------------------------------------------------------------------------
extern "C" void kernel_launch(void* const* d_in, const int* in_sizes, int n_in,
                              void* d_out, int out_size) {
    const float* weights = (const float*)d_in[0];
    const int*   src     = (const int*)d_in[1];
    const int*   dst     = (const int*)d_in[2];
    const int*   widx    = (const int*)d_in[3];
    float*       out     = (float*)d_out;

    const int EB = 1184, ET = 256;   // 8 CTAs/SM on 148 SMs
    const size_t E = (size_t)N_EDGES;

    k_start<<<1, 1>>>();
    k_edge_first<<<EB, ET>>>(src, dst, widx, weights);
    k_edge_filter<<<EB, ET>>>(src + E,   dst + E,   widx + E,   weights, 1);
    k_edge_filter<<<EB, ET>>>(src + 2*E, dst + 2*E, widx + 2*E, weights, 2);
    k_edge_last<<<EB, ET>>>(src + 3*E, dst + 3*E, widx + 3*E, weights, out);
}

// round 11
// speedup vs baseline: 1.3018x; 1.0653x over previous
#include <cuda_runtime.h>

// Problem constants (fixed by the dataset).
#define N_NEURONS 2000000u
#define N_EDGES   16000000u

// Per-lane-column bit filter: 128 words per lane-column, 32 columns (16KB).
// Word index = (sj & 127)*32 + lane  =>  bank == lane  =>  conflict-free.
// Bit index  = (sj >> 7) & 31. No hash: keys are uniform random, raw low
// bits give the same false-positive rate (~cnt/4096 ~ 2%) for free.
#define CWORDS 128
#define FILT_WORDS (CWORDS * 32)          // 4096 words = 16KB

#define TCAP (1 << 20)                    // touched-list capacity
#define ACAP (1 << 20)                    // active-list capacity

// Scratch state (allocation-free __device__ globals; zero at load, and every
// launch restores the pristine state => deterministic graph replays).
__device__ float    g_x[N_NEURONS];
__device__ float    g_out[N_NEURONS];
__device__ unsigned g_act[ACAP];
__device__ unsigned g_acnt;
__device__ unsigned g_touched[TCAP];
__device__ unsigned g_tcnt[3];
__device__ unsigned g_done[4];            // last-block tickets, self-resetting

// Scatter with touched-list registration. Exactly one adder per cell observes
// old == 0.0f; duplicate touched entries are defused by atomicExch in the tail.
__device__ __forceinline__ void scatter_edge(int d, float val, int r) {
    if (val == 0.0f) return;
    float old = atomicAdd(&g_out[d], val);
    if (old == 0.0f) {
        unsigned p = atomicAdd(&g_tcnt[r], 1u);
        if (p < TCAP) g_touched[p] = (unsigned)d;
    }
}

// Last-block election: true for every thread of the block that arrives last.
__device__ __forceinline__ bool elect_last_block(int which) {
    __shared__ unsigned s_last;
    __threadfence();
    __syncthreads();
    if (threadIdx.x == 0) {
        unsigned t = atomicAdd(&g_done[which], 1u);
        s_last = (t == gridDim.x - 1) ? 1u : 0u;
        if (s_last) g_done[which] = 0u;   // self-reset for next replay
    }
    __syncthreads();
    if (s_last) { __threadfence(); return true; }
    return false;
}

// Update tail: x += relu(out) over touched cells, out -> 0, new actives
// appended. atomicExch makes duplicate touched entries process exactly once.
__device__ void update_tail(int r, int tid, int nthr) {
    unsigned tc = g_tcnt[r];
    if (tc <= TCAP) {
        for (unsigned t = tid; t < tc; t += nthr) {
            unsigned i = g_touched[t];
            float v = atomicExch(&g_out[i], 0.0f);
            if (v > 0.0f) {
                float xo = g_x[i];
                g_x[i] = xo + v;
                if (xo == 0.0f) {
                    unsigned p = atomicAdd(&g_acnt, 1u);
                    if (p < ACAP) g_act[p] = i;
                }
            }
        }
    } else {                               // overflow fallback: full sweep
        for (unsigned i = tid; i < N_NEURONS; i += nthr) {
            float v = atomicExch(&g_out[i], 0.0f);
            if (v > 0.0f) {
                float xo = g_x[i];
                g_x[i] = xo + v;
                if (xo == 0.0f) {
                    unsigned p = atomicAdd(&g_acnt, 1u);
                    if (p < ACAP) g_act[p] = i;
                }
            }
        }
    }
}

// ---------------------------------------------------------------------------
// Start: seed x[0]=1, active={0}, counters=0.
// ---------------------------------------------------------------------------
__global__ void k_start() {
    g_x[0] = 1.0f;
    g_act[0] = 0u;
    g_acnt = 1u;
    g_tcnt[0] = 0u; g_tcnt[1] = 0u; g_tcnt[2] = 0u;
    g_out[0] = 0.0f;
}

// ---------------------------------------------------------------------------
// Layer 0: active set is exactly {0, value 1.0} -> compare only.
// ---------------------------------------------------------------------------
__global__ void __launch_bounds__(256, 8)
k_edge_first(const int* __restrict__ src, const int* __restrict__ dst,
             const int* __restrict__ widx, const float* __restrict__ weights) {
    unsigned stride = gridDim.x * blockDim.x * 8u;
    for (unsigned i = (blockIdx.x * blockDim.x + threadIdx.x) * 8u; i < N_EDGES; i += stride) {
        int4 a = __ldcs(reinterpret_cast<const int4*>(src + i));
        int4 b = __ldcs(reinterpret_cast<const int4*>(src + i + 4));
        int s[8] = {a.x, a.y, a.z, a.w, b.x, b.y, b.z, b.w};
        #pragma unroll
        for (int j = 0; j < 8; ++j) {
            if (s[j] == 0) {
                unsigned e = i + j;
                scatter_edge(__ldg(dst + e), __ldg(weights + __ldg(widx + e)), 0);
            }
        }
    }
    if (elect_last_block(0)) update_tail(0, threadIdx.x, blockDim.x);
}

// ---------------------------------------------------------------------------
// Layers 1,2: minimal-instruction bit filter. Per edge:
//   word = mycol[(sj & 127) << 5]   (conflict-free LDS, base hoisted)
//   pass = (word >> ((sj >> 7) & 31)) & 1
// On pass (true hit or ~2% false positive) gather g_x[sj] — exact either way.
// ---------------------------------------------------------------------------
__global__ void __launch_bounds__(256, 8)
k_edge_filter(const int* __restrict__ src, const int* __restrict__ dst,
              const int* __restrict__ widx, const float* __restrict__ weights,
              int round) {
    __shared__ unsigned sfilt[FILT_WORDS];

    // Zero the filter.
    for (int t = threadIdx.x; t < FILT_WORDS; t += blockDim.x) sfilt[t] = 0u;
    __syncthreads();

    // Build: every (key, column) pair sets one bit. Consecutive threads share
    // a key (broadcast) and hit consecutive lanes (conflict-free atomics).
    unsigned cnt = g_acnt;
    if (cnt > ACAP) cnt = ACAP;
    for (unsigned t = threadIdx.x; t < cnt * 32u; t += blockDim.x) {
        unsigned key = g_act[t >> 5];
        unsigned col = t & 31u;
        atomicOr(&sfilt[((key & 127u) << 5) + col], 1u << ((key >> 7) & 31u));
    }
    __syncthreads();

    const unsigned* mycol = sfilt + (threadIdx.x & 31u);
    unsigned stride = gridDim.x * blockDim.x * 8u;

    for (unsigned i = (blockIdx.x * blockDim.x + threadIdx.x) * 8u; i < N_EDGES; i += stride) {
        int4 a = __ldcs(reinterpret_cast<const int4*>(src + i));
        int4 b = __ldcs(reinterpret_cast<const int4*>(src + i + 4));
        int s[8] = {a.x, a.y, a.z, a.w, b.x, b.y, b.z, b.w};
        #pragma unroll
        for (int j = 0; j < 8; ++j) {
            unsigned sj = (unsigned)s[j];
            unsigned word = mycol[(sj & 127u) << 5];     // bank == lane
            if ((word >> ((sj >> 7) & 31u)) & 1u) {
                float xv = g_x[sj];                      // exact; 0.0 on FP
                if (xv != 0.0f) {
                    unsigned e = i + j;
                    scatter_edge(__ldg(dst + e), xv * __ldg(weights + __ldg(widx + e)), round);
                }
            }
        }
    }
    if (elect_last_block(round)) update_tail(round, threadIdx.x, blockDim.x);
}

// ---------------------------------------------------------------------------
// Layer 3: only out[0] matters -> scan dst==0, gather x[src] on the ~8 hits.
// Tail writes the final result and restores pristine global state.
// ---------------------------------------------------------------------------
__global__ void __launch_bounds__(256, 8)
k_edge_last(const int* __restrict__ src, const int* __restrict__ dst,
            const int* __restrict__ widx, const float* __restrict__ weights,
            float* __restrict__ out) {
    unsigned stride = gridDim.x * blockDim.x * 8u;
    for (unsigned i = (blockIdx.x * blockDim.x + threadIdx.x) * 8u; i < N_EDGES; i += stride) {
        int4 a = __ldcs(reinterpret_cast<const int4*>(dst + i));
        int4 b = __ldcs(reinterpret_cast<const int4*>(dst + i + 4));
        int d[8] = {a.x, a.y, a.z, a.w, b.x, b.y, b.z, b.w};
        #pragma unroll
        for (int j = 0; j < 8; ++j) {
            if (d[j] == 0) {
                unsigned e = i + j;
                atomicAdd(&g_out[0], g_x[__ldg(src + e)] * __ldg(weights + __ldg(widx + e)));
            }
        }
    }
    if (elect_last_block(3)) {
        int tid = threadIdx.x, nthr = blockDim.x;
        if (tid == 0) out[0] = g_x[0] + fmaxf(g_out[0], 0.0f);
        // Cleanup: zero every nonzero g_x cell (active list), zero g_out[0].
        unsigned ac = g_acnt;
        if (ac <= ACAP) {
            for (unsigned t = tid; t < ac; t += nthr) g_x[g_act[t]] = 0.0f;
        } else {
            for (unsigned i = tid; i < N_NEURONS; i += nthr) g_x[i] = 0.0f;
        }
        if (tid == 0) g_out[0] = 0.0f;
    }
}

// ---------------------------------------------------------------------------
// Launch sequence (graph-capturable: kernel launches only). Per-layer edge
// pointers pre-offset on the host so device indexing stays 32-bit.
// Inputs: [0]=weights f32[1024], [1]=src i32[4*16M], [2]=dst i32[4*16M],
// [3]=widx i32[4*16M]. Output: f32[1].
// ---------------------------------------------------------------------------
extern "C" void kernel_launch(void* const* d_in, const int* in_sizes, int n_in,
                              void* d_out, int out_size) {
    const float* weights = (const float*)d_in[0];
    const int*   src     = (const int*)d_in[1];
    const int*   dst     = (const int*)d_in[2];
    const int*   widx    = (const int*)d_in[3];
    float*       out     = (float*)d_out;

    const int EB = 1184, ET = 256;   // 8 CTAs/SM on 148 SMs
    const size_t E = (size_t)N_EDGES;

    k_start<<<1, 1>>>();
    k_edge_first<<<EB, ET>>>(src, dst, widx, weights);
    k_edge_filter<<<EB, ET>>>(src + E,   dst + E,   widx + E,   weights, 1);
    k_edge_filter<<<EB, ET>>>(src + 2*E, dst + 2*E, widx + 2*E, weights, 2);
    k_edge_last<<<EB, ET>>>(src + 3*E, dst + 3*E, widx + 3*E, weights, out);
}